// round 8
// baseline (speedup 1.0000x reference)
#include <cuda_runtime.h>
#include <cuda_bf16.h>
#include <cstdint>

#define NV 50000
#define NE 400000
#define CN 12500
#define NROWS 100000
#define NROWSP 100096   /* 782 * 128 */
#define NTILES 782
#define SFB 98

// ---------------- scratch (static device memory) ----------------
__device__ int   d_bar;
__device__ int   d_degcnt[NV];
__device__ float d_degF[NV];
__device__ int   d_rowptr[NV + 1];
__device__ int   d_cursor[NV];
__device__ float d_deginv[NV];
__device__ int   d_blocksums[128];
__device__ int2  d_sorted[NE];              // (end, val bits)
__device__ float d_out0[(size_t)NV * 256];  // fp32 copy of out0 for gather128 ([u][256])
__device__ float d_out1[(size_t)NV * 256];  // row (2v+b) * 128, fp32 for k_final
// bf16 hi/lo A images: [chunk][row][half][40], elem index = (chunk*NROWSP+row)*80 + half*40 + k
__device__ unsigned short d_img0[(size_t)4 * NROWSP * 80];   // L0: ch0,1 = x; ch2,3 = z0
__device__ unsigned short d_img1[(size_t)8 * NROWSP * 80];   // L1: ch0-3 = out0; ch4-7 = z1
// weight images: [chunk][n][half][40]
__device__ unsigned short d_Wimg0[4 * 128 * 80];
__device__ unsigned short d_Wimg1[8 * 128 * 80];

// ---------------- helpers ----------------
__device__ __forceinline__ uint32_t smem_u32(const void* p) {
    uint32_t a;
    asm("{ .reg .u64 t; cvta.to.shared.u64 t, %1; cvt.u32.u64 %0, t; }" : "=r"(a) : "l"(p));
    return a;
}
__device__ __forceinline__ void ldmat4(uint32_t* r, uint32_t addr) {
    asm volatile("ldmatrix.sync.aligned.m8n8.x4.shared.b16 {%0,%1,%2,%3}, [%4];"
                 : "=r"(r[0]), "=r"(r[1]), "=r"(r[2]), "=r"(r[3]) : "r"(addr));
}
__device__ __forceinline__ void mma_bf16(float* d, const uint32_t* a, const uint32_t* b) {
    asm volatile("mma.sync.aligned.m16n8k16.row.col.f32.bf16.bf16.f32 "
                 "{%0,%1,%2,%3}, {%4,%5,%6,%7}, {%8,%9}, {%0,%1,%2,%3};"
                 : "+f"(d[0]), "+f"(d[1]), "+f"(d[2]), "+f"(d[3])
                 : "r"(a[0]), "r"(a[1]), "r"(a[2]), "r"(a[3]), "r"(b[0]), "r"(b[1]));
}
__device__ __forceinline__ void cpa16(uint32_t dst, const void* src) {
    asm volatile("cp.async.cg.shared.global [%0], [%1], 16;" :: "r"(dst), "l"(src) : "memory");
}
#define CPA_COMMIT() asm volatile("cp.async.commit_group;" ::: "memory")
#define CPA_WAIT0()  asm volatile("cp.async.wait_group 0;" ::: "memory")
#define CPA_WAIT1()  asm volatile("cp.async.wait_group 1;" ::: "memory")

__device__ __forceinline__ float bfhi(float x) {
    return __bfloat162float(__float2bfloat16(x));
}
__device__ __forceinline__ unsigned short bfb(float x) {
    return __bfloat16_as_ushort(__float2bfloat16(x));
}
__device__ __forceinline__ uint32_t pk(float a, float b) {
    return (uint32_t)bfb(a) | ((uint32_t)bfb(b) << 16);
}

// software grid barrier (SFB blocks co-resident by construction)
__device__ __forceinline__ void gbar(int target) {
    __syncthreads();
    __threadfence();
    if (threadIdx.x == 0) {
        atomicAdd(&d_bar, 1);
        while (atomicAdd(&d_bar, 0) < target) { }
    }
    __syncthreads();
    __threadfence();
}

// ---------------- k_prep: zero scratch + build bf16 hi/lo weight images ----------------
__global__ void k_prep(const float* __restrict__ W0s, const float* __restrict__ W0n,
                       const float* __restrict__ W1s, const float* __restrict__ W1n) {
    int gt = blockIdx.x * blockDim.x + threadIdx.x;
    int stride = gridDim.x * blockDim.x;
    if (gt == 0) d_bar = 0;
    for (int i = gt; i < NV; i += stride) {
        d_degcnt[i] = 0; d_degF[i] = 0.f; d_cursor[i] = 0;
    }
    for (int it = gt; it < 49152; it += stride) {
        bool isL1 = it >= 16384;
        int loc = isL1 ? (it - 16384) : it;
        int c = loc >> 12;
        int rem = loc & 4095;
        int n = rem >> 5;
        int kl = rem & 31;
        int k = c * 32 + kl;
        float v;
        if (isL1) v = (k < 128) ? W1s[(size_t)k * 128 + n] : W1n[(size_t)(k - 128) * 128 + n];
        else      v = (k < 64)  ? W0s[(size_t)k * 128 + n] : W0n[(size_t)(k - 64) * 128 + n];
        float hi = bfhi(v);
        unsigned short* img = isL1 ? d_Wimg1 : d_Wimg0;
        img[(size_t)(c * 128 + n) * 80 + kl]      = bfb(v);
        img[(size_t)(c * 128 + n) * 80 + 40 + kl] = bfb(v - hi);
    }
}

// ---------------- k_hist ----------------
__global__ void k_hist(const int* __restrict__ Es, const float* __restrict__ one) {
    int e = blockIdx.x * blockDim.x + threadIdx.x;
    if (e < NE) {
        int s = Es[e];
        atomicAdd(&d_degcnt[s], 1);
        atomicAdd(&d_degF[s], one[e]);
    }
}

// ---------------- k_convx: x fp32 -> hi/lo image (img0 chunks 0,1) ----------------
__global__ void __launch_bounds__(256) k_convx(const float* __restrict__ x) {
    int gt = blockIdx.x * 256 + threadIdx.x;   // exactly NROWS*16 threads
    int row = gt >> 4, kq = (gt & 15) * 4;
    float4 v = *(const float4*)(x + ((size_t)(row & 1) * NV + (row >> 1)) * 64 + kq);
    int ch = kq >> 5, kl = kq & 31;
    size_t wb = ((size_t)ch * NROWSP + row) * 80 + kl;
    *(uint2*)(d_img0 + wb)      = make_uint2(pk(v.x, v.y), pk(v.z, v.w));
    *(uint2*)(d_img0 + wb + 40) = make_uint2(pk(v.x - bfhi(v.x), v.y - bfhi(v.y)),
                                             pk(v.z - bfhi(v.z), v.w - bfhi(v.w)));
}

// ---------------- k_scanfill: scan -> fixup -> CSR fill (grid barriers) ----------------
__global__ void __launch_bounds__(512) k_scanfill(const int* __restrict__ Es,
                                                  const int* __restrict__ Ee,
                                                  const float* __restrict__ adj) {
    __shared__ int s[512];
    const int NT = SFB * 512;
    int tid = threadIdx.x;
    int gt = blockIdx.x * 512 + tid;

    int val = (gt < NV) ? d_degcnt[gt] : 0;
    s[tid] = val;
    __syncthreads();
    for (int off = 1; off < 512; off <<= 1) {
        int t = (tid >= off) ? s[tid - off] : 0;
        __syncthreads();
        s[tid] += t;
        __syncthreads();
    }
    if (gt < NV) d_rowptr[gt + 1] = s[tid];
    if (tid == 511) d_blocksums[blockIdx.x] = s[511];
    gbar(SFB);

    {
        s[tid] = (tid < SFB) ? d_blocksums[tid] : 0;
        __syncthreads();
        for (int off = 1; off < 512; off <<= 1) {
            int u = (tid >= off) ? s[tid - off] : 0;
            __syncthreads();
            s[tid] += u;
            __syncthreads();
        }
        int boff = (blockIdx.x > 0) ? s[blockIdx.x - 1] : 0;
        if (gt < NV) {
            d_rowptr[gt + 1] += boff;
            d_deginv[gt] = 1.0f / fmaxf(d_degF[gt], 1.0f);
        }
        if (gt == 0) d_rowptr[0] = 0;
    }
    gbar(2 * SFB);

    for (int e = gt; e < NE; e += NT) {
        int src = Es[e];
        int p = atomicAdd(&d_cursor[src], 1);
        d_sorted[d_rowptr[src] + p] = make_int2(Ee[e], __float_as_int(adj[e]));
    }
}

// ---------------- gather64: warp/node, reads x fp32, writes z0 hi/lo image ----------------
__global__ void __launch_bounds__(256) k_gather64(const float* __restrict__ x) {
    int v = blockIdx.x * 8 + (threadIdx.x >> 5);
    int lane = threadIdx.x & 31;
    int b = lane >> 4, k = (lane & 15) * 4;
    const float* xb = x + ((size_t)b * NV) * 64 + k;
    int i = d_rowptr[v], end = d_rowptr[v + 1];
    float4 acc = make_float4(0.f, 0.f, 0.f, 0.f);
    for (; i + 2 <= end; i += 2) {
        int2 e0 = d_sorted[i];
        int2 e1 = d_sorted[i + 1];
        float w0 = __int_as_float(e0.y), w1 = __int_as_float(e1.y);
        float4 f0 = *(const float4*)(xb + (size_t)e0.x * 64);
        float4 f1 = *(const float4*)(xb + (size_t)e1.x * 64);
        acc.x = fmaf(w0, f0.x, fmaf(w1, f1.x, acc.x));
        acc.y = fmaf(w0, f0.y, fmaf(w1, f1.y, acc.y));
        acc.z = fmaf(w0, f0.z, fmaf(w1, f1.z, acc.z));
        acc.w = fmaf(w0, f0.w, fmaf(w1, f1.w, acc.w));
    }
    if (i < end) {
        int2 e0 = d_sorted[i];
        float w0 = __int_as_float(e0.y);
        float4 f0 = *(const float4*)(xb + (size_t)e0.x * 64);
        acc.x = fmaf(w0, f0.x, acc.x);
        acc.y = fmaf(w0, f0.y, acc.y);
        acc.z = fmaf(w0, f0.z, acc.z);
        acc.w = fmaf(w0, f0.w, acc.w);
    }
    float di = d_deginv[v];
    acc.x *= di; acc.y *= di; acc.z *= di; acc.w *= di;
    int ch = 2 + (k >> 5), kl = k & 31;
    size_t wb = ((size_t)ch * NROWSP + 2 * v + b) * 80 + kl;
    *(uint2*)(d_img0 + wb)      = make_uint2(pk(acc.x, acc.y), pk(acc.z, acc.w));
    *(uint2*)(d_img0 + wb + 40) = make_uint2(pk(acc.x - bfhi(acc.x), acc.y - bfhi(acc.y)),
                                             pk(acc.z - bfhi(acc.z), acc.w - bfhi(acc.w)));
}

// ---------------- gather128: reads out0 fp32 (fast 16B loads), writes z1 image ----------------
__global__ void __launch_bounds__(256) k_gather128() {
    int v = blockIdx.x * 8 + (threadIdx.x >> 5);
    int lane = threadIdx.x & 31;
    int i = d_rowptr[v], end = d_rowptr[v + 1];
    float4 a0 = make_float4(0.f, 0.f, 0.f, 0.f);
    float4 a1 = make_float4(0.f, 0.f, 0.f, 0.f);
    for (; i + 2 <= end; i += 2) {
        int2 e0 = d_sorted[i];
        int2 e1 = d_sorted[i + 1];
        float w0 = __int_as_float(e0.y), w1 = __int_as_float(e1.y);
        const float* s0 = d_out0 + (size_t)e0.x * 256 + lane * 4;
        const float* s1 = d_out0 + (size_t)e1.x * 256 + lane * 4;
        float4 f0 = *(const float4*)(s0);
        float4 g0 = *(const float4*)(s0 + 128);
        float4 f1 = *(const float4*)(s1);
        float4 g1 = *(const float4*)(s1 + 128);
        a0.x = fmaf(w0, f0.x, fmaf(w1, f1.x, a0.x));
        a0.y = fmaf(w0, f0.y, fmaf(w1, f1.y, a0.y));
        a0.z = fmaf(w0, f0.z, fmaf(w1, f1.z, a0.z));
        a0.w = fmaf(w0, f0.w, fmaf(w1, f1.w, a0.w));
        a1.x = fmaf(w0, g0.x, fmaf(w1, g1.x, a1.x));
        a1.y = fmaf(w0, g0.y, fmaf(w1, g1.y, a1.y));
        a1.z = fmaf(w0, g0.z, fmaf(w1, g1.z, a1.z));
        a1.w = fmaf(w0, g0.w, fmaf(w1, g1.w, a1.w));
    }
    if (i < end) {
        int2 e0 = d_sorted[i];
        float w0 = __int_as_float(e0.y);
        const float* s0 = d_out0 + (size_t)e0.x * 256 + lane * 4;
        float4 f0 = *(const float4*)(s0);
        float4 g0 = *(const float4*)(s0 + 128);
        a0.x = fmaf(w0, f0.x, a0.x); a0.y = fmaf(w0, f0.y, a0.y);
        a0.z = fmaf(w0, f0.z, a0.z); a0.w = fmaf(w0, f0.w, a0.w);
        a1.x = fmaf(w0, g0.x, a1.x); a1.y = fmaf(w0, g0.y, a1.y);
        a1.z = fmaf(w0, g0.z, a1.z); a1.w = fmaf(w0, g0.w, a1.w);
    }
    float di = d_deginv[v];
    a0.x *= di; a0.y *= di; a0.z *= di; a0.w *= di;
    a1.x *= di; a1.y *= di; a1.z *= di; a1.w *= di;
    int ch = 4 + (lane >> 3);
    int kl = (lane & 7) * 4;
    size_t wb = ((size_t)ch * NROWSP + 2 * v) * 80 + kl;
    *(uint2*)(d_img1 + wb)       = make_uint2(pk(a0.x, a0.y), pk(a0.z, a0.w));
    *(uint2*)(d_img1 + wb + 40)  = make_uint2(pk(a0.x - bfhi(a0.x), a0.y - bfhi(a0.y)),
                                              pk(a0.z - bfhi(a0.z), a0.w - bfhi(a0.w)));
    *(uint2*)(d_img1 + wb + 80)  = make_uint2(pk(a1.x, a1.y), pk(a1.z, a1.w));
    *(uint2*)(d_img1 + wb + 120) = make_uint2(pk(a1.x - bfhi(a1.x), a1.y - bfhi(a1.y)),
                                              pk(a1.z - bfhi(a1.z), a1.w - bfhi(a1.w)));
}

// ---------------- tensor-core GEMM: cp.async 2-stage pipeline, pass-major MMA ----------------
template <int NCH, bool L0F>
__global__ void __launch_bounds__(256, 2) k_gemm(const float* __restrict__ bias) {
    extern __shared__ unsigned char sm[];
    const int SA = 1024;
    const int SB = 1024 + 2 * 20480;
    int tid = threadIdx.x;
    int wid = tid >> 5, lane = tid & 31;
    int tile = blockIdx.x;
    int wm = (wid & 3) * 32, wn = (wid >> 2) * 64;
    uint32_t smb = smem_u32(sm);
    const unsigned short* aimg = L0F ? d_img0 : d_img1;
    const unsigned short* wimg = L0F ? d_Wimg0 : d_Wimg1;

    int half = tid >> 7, rowl = tid & 127;
    const unsigned short* asrc0 = aimg + (size_t)(tile * 128 + rowl) * 80 + half * 40;
    const unsigned short* bsrc0 = wimg + rowl * 80 + half * 40;
    uint32_t dsto = (uint32_t)((half * 5120 + rowl * 40) * 2);

    auto prefetch = [&](int c, int s) {
        const unsigned short* asrc = asrc0 + (size_t)c * ((size_t)NROWSP * 80);
        const unsigned short* bsrc = bsrc0 + c * (128 * 80);
        uint32_t adst = smb + SA + s * 20480 + dsto;
        uint32_t bdst = smb + SB + s * 20480 + dsto;
#pragma unroll
        for (int q = 0; q < 5; q++) {
            cpa16(adst + q * 16, asrc + q * 8);
            cpa16(bdst + q * 16, bsrc + q * 8);
        }
        CPA_COMMIT();
    };

    if (tid < 128) ((float*)sm)[tid] = bias[tid];

    float acc[2][8][4];
#pragma unroll
    for (int m = 0; m < 2; m++)
#pragma unroll
        for (int nf = 0; nf < 8; nf++)
#pragma unroll
            for (int q = 0; q < 4; q++) acc[m][nf][q] = 0.f;

    int a_r = wm + (lane & 15);
    int a_k = (lane >> 4) << 3;
    int b_n = wn + (lane & 7) + ((lane >> 4) << 3);
    int b_k = ((lane >> 3) & 1) << 3;

    auto compute = [&](int s) {
        uint32_t aB = smb + SA + s * 20480;
        uint32_t bB = smb + SB + s * 20480;
#pragma unroll
        for (int ks = 0; ks < 2; ks++) {
            int k0 = ks * 16;
            uint32_t ahi[2][4], alo[2][4];
#pragma unroll
            for (int m = 0; m < 2; m++) {
                uint32_t ad = aB + (uint32_t)(((a_r + m * 16) * 40 + k0 + a_k) * 2);
                ldmat4(ahi[m], ad);
                ldmat4(alo[m], ad + 10240);
            }
            uint32_t bhi[8][2], blo[8][2];
#pragma unroll
            for (int g = 0; g < 4; g++) {
                uint32_t bd = bB + (uint32_t)(((b_n + g * 16) * 40 + k0 + b_k) * 2);
                uint32_t t[4];
                ldmat4(t, bd);
                bhi[2 * g][0] = t[0]; bhi[2 * g][1] = t[1];
                bhi[2 * g + 1][0] = t[2]; bhi[2 * g + 1][1] = t[3];
                ldmat4(t, bd + 10240);
                blo[2 * g][0] = t[0]; blo[2 * g][1] = t[1];
                blo[2 * g + 1][0] = t[2]; blo[2 * g + 1][1] = t[3];
            }
            // pass-major: accumulator reuse distance = 16 MMAs (no RAW stalls)
#pragma unroll
            for (int m = 0; m < 2; m++)
#pragma unroll
                for (int nf = 0; nf < 8; nf++) mma_bf16(acc[m][nf], ahi[m], bhi[nf]);
#pragma unroll
            for (int m = 0; m < 2; m++)
#pragma unroll
                for (int nf = 0; nf < 8; nf++) mma_bf16(acc[m][nf], alo[m], bhi[nf]);
#pragma unroll
            for (int m = 0; m < 2; m++)
#pragma unroll
                for (int nf = 0; nf < 8; nf++) mma_bf16(acc[m][nf], ahi[m], blo[nf]);
        }
    };

    prefetch(0, 0);
    prefetch(1, 1);
#pragma unroll
    for (int c = 0; c < NCH; c++) {
        if (c < NCH - 1) { CPA_WAIT1(); } else { CPA_WAIT0(); }
        __syncthreads();
        compute(c & 1);
        __syncthreads();
        if (c + 2 < NCH) prefetch(c + 2, c & 1);
    }

    // epilogue
    const float* sbias = (const float*)sm;
#pragma unroll
    for (int m = 0; m < 2; m++) {
        int r0 = tile * 128 + wm + m * 16 + (lane >> 2);
#pragma unroll
        for (int nf = 0; nf < 8; nf++) {
            int col = wn + nf * 8 + (lane & 3) * 2;
            float bx = sbias[col], by = sbias[col + 1];
            float o0 = acc[m][nf][0] + bx, o1 = acc[m][nf][1] + by;
            float o2 = acc[m][nf][2] + bx, o3 = acc[m][nf][3] + by;
            if (L0F) {
                o0 = (o0 >= 0.f) ? o0 : 0.2f * o0;
                o1 = (o1 >= 0.f) ? o1 : 0.2f * o1;
                o2 = (o2 >= 0.f) ? o2 : 0.2f * o2;
                o3 = (o3 >= 0.f) ? o3 : 0.2f * o3;
                int ch = col >> 5, kl = col & 31;
                if (r0 < NROWS) {
                    *(float2*)(d_out0 + (size_t)r0 * 128 + col) = make_float2(o0, o1);
                    size_t base = ((size_t)ch * NROWSP + r0) * 80 + kl;
                    *(uint32_t*)(d_img1 + base)      = pk(o0, o1);
                    *(uint32_t*)(d_img1 + base + 40) = pk(o0 - bfhi(o0), o1 - bfhi(o1));
                }
                if (r0 + 8 < NROWS) {
                    *(float2*)(d_out0 + (size_t)(r0 + 8) * 128 + col) = make_float2(o2, o3);
                    size_t base = ((size_t)ch * NROWSP + r0 + 8) * 80 + kl;
                    *(uint32_t*)(d_img1 + base)      = pk(o2, o3);
                    *(uint32_t*)(d_img1 + base + 40) = pk(o2 - bfhi(o2), o3 - bfhi(o3));
                }
            } else {
                if (r0 < NROWS)     *(float2*)(d_out1 + (size_t)r0 * 128 + col)       = make_float2(o0, o1);
                if (r0 + 8 < NROWS) *(float2*)(d_out1 + (size_t)(r0 + 8) * 128 + col) = make_float2(o2, o3);
            }
        }
    }
}

// ---------------- final: pool(out1) + (pool(x) @ W_res + sw * b_res) ----------------
__global__ void __launch_bounds__(256) k_final(const float* __restrict__ x,
                                               const int* __restrict__ asgnIdx,
                                               const float* __restrict__ asgnVal,
                                               const float* __restrict__ Wres,
                                               const float* __restrict__ bres,
                                               float* __restrict__ out) {
    __shared__ float xps[4][64];
    int sub = threadIdx.x >> 6;
    int p = threadIdx.x & 63;
    int r = blockIdx.x * 4 + sub;
    bool ok = r < 2 * CN;
    int c = r >> 1, b = r & 1;
    const int* fine = asgnIdx + NV;
    float sw = 0.f;
    float2 p1 = make_float2(0.f, 0.f);
    if (ok) {
        int i0 = 4 * c;
        float a = 0.f;
#pragma unroll
        for (int j = 0; j < 4; j++) {
            int f = fine[i0 + j];
            float w = asgnVal[i0 + j];
            a = fmaf(w, x[((size_t)b * NV + f) * 64 + p], a);
            sw += w;
            float2 o1 = *(const float2*)(&d_out1[((size_t)(2 * f + b)) * 128 + 2 * p]);
            p1.x = fmaf(w, o1.x, p1.x);
            p1.y = fmaf(w, o1.y, p1.y);
        }
        xps[sub][p] = a;
    }
    __syncthreads();
    if (ok) {
        float2 br = *(const float2*)(bres + 2 * p);
        float accx = p1.x + sw * br.x;
        float accy = p1.y + sw * br.y;
#pragma unroll 8
        for (int k = 0; k < 64; k++) {
            float xk = xps[sub][k];
            float2 w2 = *(const float2*)(Wres + k * 128 + 2 * p);
            accx = fmaf(xk, w2.x, accx);
            accy = fmaf(xk, w2.y, accy);
        }
        *(float2*)(out + ((size_t)b * CN + c) * 128 + 2 * p) = make_float2(accx, accy);
    }
}

// ---------------- launch ----------------
extern "C" void kernel_launch(void* const* d_in, const int* in_sizes, int n_in,
                              void* d_out, int out_size) {
    const float* x       = (const float*)d_in[0];
    const float* adjVal  = (const float*)d_in[1];
    const float* edgeOne = (const float*)d_in[2];
    const int*   E_start = (const int*)d_in[3];
    const int*   E_end   = (const int*)d_in[4];
    const int*   asgnIdx = (const int*)d_in[5];
    const float* asgnVal = (const float*)d_in[6];
    const float* W_res   = (const float*)d_in[7];
    const float* b_res   = (const float*)d_in[8];
    const float* W0s     = (const float*)d_in[9];
    const float* W0n     = (const float*)d_in[10];
    const float* b0      = (const float*)d_in[11];
    const float* W1s     = (const float*)d_in[12];
    const float* W1n     = (const float*)d_in[13];
    const float* b1      = (const float*)d_in[14];
    float* out = (float*)d_out;

    const int smG = 1024 + 4 * 20480;   // 82944 -> 2 CTAs/SM
    cudaFuncSetAttribute(k_gemm<4, true>,  cudaFuncAttributeMaxDynamicSharedMemorySize, smG);
    cudaFuncSetAttribute(k_gemm<8, false>, cudaFuncAttributeMaxDynamicSharedMemorySize, smG);

    k_prep<<<64, 256>>>(W0s, W0n, W1s, W1n);                       // 0
    k_hist<<<(NE + 255) / 256, 256>>>(E_start, edgeOne);           // 1
    k_convx<<<(NROWS * 16) / 256, 256>>>(x);                       // 2
    k_scanfill<<<SFB, 512>>>(E_start, E_end, adjVal);              // 3
    k_gather64<<<NV / 8, 256>>>(x);                                // 4
    k_gemm<4, true><<<NTILES, 256, smG>>>(b0);                     // 5
    k_gather128<<<NV / 8, 256>>>();                                // 6
    k_gemm<8, false><<<NTILES, 256, smG>>>(b1);                    // 7
    k_final<<<(2 * CN + 3) / 4, 256>>>(x, asgnIdx, asgnVal, W_res, b_res, out); // 8
}

// round 9
// speedup vs baseline: 1.5151x; 1.5151x over previous
#include <cuda_runtime.h>
#include <cuda_fp16.h>
#include <cstdint>

#define NV 50000
#define NE 400000
#define CN 12500
#define NROWS 100000
#define NTILES 782      /* ceil(100000/128) */
#define BST 72          /* fp16 elems per smem row (64 data + 8 pad) */
#define SFB 98          /* scanfill blocks */
#define PPB 148         /* prep blocks (one per SM, co-resident) */

// ---------------- scratch (static device memory) ----------------
__device__ int   d_barA;
__device__ int   d_barB;
__device__ int   d_degcnt[NV];
__device__ float d_degF[NV];
__device__ int   d_rowptr[NV + 1];
__device__ int   d_cursor[NV];
__device__ float d_deginv[NV];
__device__ int   d_blocksums[128];
__device__ int2  d_sorted[NE];              // (end, val bits)
__device__ float d_z0[(size_t)NV * 128];    // [v][b*64+k]
__device__ float d_out0[(size_t)NV * 256];  // row (2v+b) * 128
__device__ float d_z1[(size_t)NV * 256];
__device__ float d_out1[(size_t)NV * 256];
// fp16 weight images (hi only), per-chunk 128 n rows x BST: [chunk][n][BST]
__device__ unsigned short d_Wimg0[2 * 128 * BST];
__device__ unsigned short d_Wimg1[4 * 128 * BST];

// ---------------- helpers ----------------
__device__ __forceinline__ uint32_t smem_u32(const void* p) {
    uint32_t a;
    asm("{ .reg .u64 t; cvta.to.shared.u64 t, %1; cvt.u32.u64 %0, t; }" : "=r"(a) : "l"(p));
    return a;
}
__device__ __forceinline__ void ldmat4(uint32_t* r, uint32_t addr) {
    asm volatile("ldmatrix.sync.aligned.m8n8.x4.shared.b16 {%0,%1,%2,%3}, [%4];"
                 : "=r"(r[0]), "=r"(r[1]), "=r"(r[2]), "=r"(r[3]) : "r"(addr));
}
__device__ __forceinline__ void mma_f16(float* d, const uint32_t* a, const uint32_t* b) {
    asm volatile("mma.sync.aligned.m16n8k16.row.col.f32.f16.f16.f32 "
                 "{%0,%1,%2,%3}, {%4,%5,%6,%7}, {%8,%9}, {%0,%1,%2,%3};"
                 : "+f"(d[0]), "+f"(d[1]), "+f"(d[2]), "+f"(d[3])
                 : "r"(a[0]), "r"(a[1]), "r"(a[2]), "r"(a[3]), "r"(b[0]), "r"(b[1]));
}
__device__ __forceinline__ void cpa16(uint32_t dst, const void* src) {
    asm volatile("cp.async.cg.shared.global [%0], [%1], 16;" :: "r"(dst), "l"(src) : "memory");
}
#define CPA_COMMIT() asm volatile("cp.async.commit_group;" ::: "memory")
#define CPA_WAIT0()  asm volatile("cp.async.wait_group 0;" ::: "memory")
#define CPA_WAIT1()  asm volatile("cp.async.wait_group 1;" ::: "memory")

__device__ __forceinline__ float hhi(float x) {
    return __half2float(__float2half_rn(x));
}
__device__ __forceinline__ unsigned short hfb(float x) {
    return __half_as_ushort(__float2half_rn(x));
}
__device__ __forceinline__ uint32_t pkh(float a, float b) {
    return (uint32_t)hfb(a) | ((uint32_t)hfb(b) << 16);
}

// software grid barrier over a counter (all blocks co-resident by construction)
__device__ __forceinline__ void gbar(int* ctr, int target) {
    __syncthreads();
    __threadfence();
    if (threadIdx.x == 0) {
        atomicAdd(ctr, 1);
        while (atomicAdd(ctr, 0) < target) { }
    }
    __syncthreads();
    __threadfence();
}

// ---------------- k_prep: zero scratch + fp16 weight images + (gbar) + hist ----------------
__global__ void __launch_bounds__(256) k_prep(const float* __restrict__ W0s, const float* __restrict__ W0n,
                                              const float* __restrict__ W1s, const float* __restrict__ W1n,
                                              const int* __restrict__ Es, const float* __restrict__ one) {
    int gt = blockIdx.x * blockDim.x + threadIdx.x;
    const int stride = PPB * 256;
    for (int i = gt; i < NV; i += stride) {
        d_degcnt[i] = 0; d_degF[i] = 0.f; d_cursor[i] = 0;
    }
    // weight items: L0 = 2 chunks * 128 n * 64 k = 16384; L1 = 4 chunks -> 32768
    for (int it = gt; it < 49152; it += stride) {
        bool isL1 = it >= 16384;
        int loc = isL1 ? (it - 16384) : it;
        int c = loc >> 13;
        int rem = loc & 8191;
        int n = rem >> 6;
        int kl = rem & 63;
        int k = c * 64 + kl;
        float v;
        if (isL1) v = (k < 128) ? W1s[(size_t)k * 128 + n] : W1n[(size_t)(k - 128) * 128 + n];
        else      v = (k < 64)  ? W0s[(size_t)k * 128 + n] : W0n[(size_t)(k - 64) * 128 + n];
        unsigned short* img = isL1 ? d_Wimg1 : d_Wimg0;
        img[(size_t)(c * 128 + n) * BST + kl] = hfb(v);
    }
    gbar(&d_barA, PPB);
    // histogram
    for (int e = gt; e < NE; e += stride) {
        int s = Es[e];
        atomicAdd(&d_degcnt[s], 1);
        atomicAdd(&d_degF[s], one[e]);
    }
}

// ---------------- k_scanfill: scan -> fixup -> CSR fill (grid barriers) ----------------
__global__ void __launch_bounds__(512) k_scanfill(const int* __restrict__ Es,
                                                  const int* __restrict__ Ee,
                                                  const float* __restrict__ adj) {
    __shared__ int s[512];
    const int NT = SFB * 512;
    int tid = threadIdx.x;
    int gt = blockIdx.x * 512 + tid;

    int val = (gt < NV) ? d_degcnt[gt] : 0;
    s[tid] = val;
    __syncthreads();
    for (int off = 1; off < 512; off <<= 1) {
        int t = (tid >= off) ? s[tid - off] : 0;
        __syncthreads();
        s[tid] += t;
        __syncthreads();
    }
    if (gt < NV) d_rowptr[gt + 1] = s[tid];
    if (tid == 511) d_blocksums[blockIdx.x] = s[511];
    gbar(&d_barB, SFB);

    {
        s[tid] = (tid < SFB) ? d_blocksums[tid] : 0;
        __syncthreads();
        for (int off = 1; off < 512; off <<= 1) {
            int u = (tid >= off) ? s[tid - off] : 0;
            __syncthreads();
            s[tid] += u;
            __syncthreads();
        }
        int boff = (blockIdx.x > 0) ? s[blockIdx.x - 1] : 0;
        if (gt < NV) {
            d_rowptr[gt + 1] += boff;
            d_deginv[gt] = 1.0f / fmaxf(d_degF[gt], 1.0f);
        }
        if (gt == 0) d_rowptr[0] = 0;
    }
    gbar(&d_barB, 2 * SFB);

    for (int e = gt; e < NE; e += NT) {
        int src = Es[e];
        int p = atomicAdd(&d_cursor[src], 1);
        d_sorted[d_rowptr[src] + p] = make_int2(Ee[e], __float_as_int(adj[e]));
    }
}

// ---------------- gather64: warp per node, float4 per lane, unroll-2 ----------------
__global__ void __launch_bounds__(256) k_gather64(const float* __restrict__ x) {
    int v = blockIdx.x * 8 + (threadIdx.x >> 5);
    int lane = threadIdx.x & 31;
    int b = lane >> 4, k = (lane & 15) * 4;
    const float* xb = x + ((size_t)b * NV) * 64 + k;
    int i = d_rowptr[v], end = d_rowptr[v + 1];
    float4 acc = make_float4(0.f, 0.f, 0.f, 0.f);
    for (; i + 2 <= end; i += 2) {
        int2 e0 = d_sorted[i];
        int2 e1 = d_sorted[i + 1];
        float w0 = __int_as_float(e0.y), w1 = __int_as_float(e1.y);
        float4 f0 = *(const float4*)(xb + (size_t)e0.x * 64);
        float4 f1 = *(const float4*)(xb + (size_t)e1.x * 64);
        acc.x = fmaf(w0, f0.x, fmaf(w1, f1.x, acc.x));
        acc.y = fmaf(w0, f0.y, fmaf(w1, f1.y, acc.y));
        acc.z = fmaf(w0, f0.z, fmaf(w1, f1.z, acc.z));
        acc.w = fmaf(w0, f0.w, fmaf(w1, f1.w, acc.w));
    }
    if (i < end) {
        int2 e0 = d_sorted[i];
        float w0 = __int_as_float(e0.y);
        float4 f0 = *(const float4*)(xb + (size_t)e0.x * 64);
        acc.x = fmaf(w0, f0.x, acc.x);
        acc.y = fmaf(w0, f0.y, acc.y);
        acc.z = fmaf(w0, f0.z, acc.z);
        acc.w = fmaf(w0, f0.w, acc.w);
    }
    float di = d_deginv[v];
    acc.x *= di; acc.y *= di; acc.z *= di; acc.w *= di;
    *(float4*)(d_z0 + (size_t)v * 128 + lane * 4) = acc;
}

__global__ void __launch_bounds__(256) k_gather128() {
    int v = blockIdx.x * 8 + (threadIdx.x >> 5);
    int lane = threadIdx.x & 31;
    int i = d_rowptr[v], end = d_rowptr[v + 1];
    float4 a0 = make_float4(0.f, 0.f, 0.f, 0.f);
    float4 a1 = make_float4(0.f, 0.f, 0.f, 0.f);
    for (; i + 2 <= end; i += 2) {
        int2 e0 = d_sorted[i];
        int2 e1 = d_sorted[i + 1];
        float w0 = __int_as_float(e0.y), w1 = __int_as_float(e1.y);
        const float* s0 = d_out0 + (size_t)e0.x * 256 + lane * 4;
        const float* s1 = d_out0 + (size_t)e1.x * 256 + lane * 4;
        float4 f0 = *(const float4*)(s0);
        float4 g0 = *(const float4*)(s0 + 128);
        float4 f1 = *(const float4*)(s1);
        float4 g1 = *(const float4*)(s1 + 128);
        a0.x = fmaf(w0, f0.x, fmaf(w1, f1.x, a0.x));
        a0.y = fmaf(w0, f0.y, fmaf(w1, f1.y, a0.y));
        a0.z = fmaf(w0, f0.z, fmaf(w1, f1.z, a0.z));
        a0.w = fmaf(w0, f0.w, fmaf(w1, f1.w, a0.w));
        a1.x = fmaf(w0, g0.x, fmaf(w1, g1.x, a1.x));
        a1.y = fmaf(w0, g0.y, fmaf(w1, g1.y, a1.y));
        a1.z = fmaf(w0, g0.z, fmaf(w1, g1.z, a1.z));
        a1.w = fmaf(w0, g0.w, fmaf(w1, g1.w, a1.w));
    }
    if (i < end) {
        int2 e0 = d_sorted[i];
        float w0 = __int_as_float(e0.y);
        const float* s0 = d_out0 + (size_t)e0.x * 256 + lane * 4;
        float4 f0 = *(const float4*)(s0);
        float4 g0 = *(const float4*)(s0 + 128);
        a0.x = fmaf(w0, f0.x, a0.x); a0.y = fmaf(w0, f0.y, a0.y);
        a0.z = fmaf(w0, f0.z, a0.z); a0.w = fmaf(w0, f0.w, a0.w);
        a1.x = fmaf(w0, g0.x, a1.x); a1.y = fmaf(w0, g0.y, a1.y);
        a1.z = fmaf(w0, g0.z, a1.z); a1.w = fmaf(w0, g0.w, a1.w);
    }
    float di = d_deginv[v];
    a0.x *= di; a0.y *= di; a0.z *= di; a0.w *= di;
    a1.x *= di; a1.y *= di; a1.z *= di; a1.w *= di;
    *(float4*)(d_z1 + (size_t)v * 256 + lane * 4)       = a0;
    *(float4*)(d_z1 + (size_t)v * 256 + 128 + lane * 4) = a1;
}

// ---------------- tensor-core concat-GEMM (fp16 A-split 2-pass compensated) ----------------
// CTA 128x128, chunk-64 K. smem: bias 1024 + A buf 36864 (hi+lo planes) + B stages 2x18432 (hi only).
// A: fp32 loaded with partial register prefetch, converted to fp16 hi/lo in-kernel.
// B: pre-converted fp16 image streamed via cp.async double buffer.
template <int NC, bool L0F>
__global__ void __launch_bounds__(256, 2) k_gemm(const float* __restrict__ xin,
                                                 const float* __restrict__ bias) {
    extern __shared__ unsigned char sm[];
    const int SA = 1024;
    const int SB = 1024 + 36864;
    int tid = threadIdx.x;
    int wid = tid >> 5, lane = tid & 31;
    int tile = blockIdx.x;
    int wm = (wid & 3) * 32, wn = (wid >> 2) * 64;
    uint32_t smb = smem_u32(sm);
    const unsigned short* wimg = L0F ? d_Wimg0 : d_Wimg1;

    auto prefetchB = [&](int c, int stage) {
        const unsigned char* src = (const unsigned char*)(wimg + (size_t)c * (128 * BST));
        uint32_t dst = smb + SB + stage * 18432;
#pragma unroll
        for (int i = 0; i < 5; i++) {
            int seg = tid + i * 256;
            if (seg < 1152) cpa16(dst + seg * 16, src + seg * 16);
        }
        CPA_COMMIT();
    };

    if (tid < 128) ((float*)sm)[tid] = bias[tid];

    // A loaders: thread covers row arow, k in [kq, kq+32)
    int arow = tid >> 1;
    int kq = (tid & 1) * 32;
    int row = tile * 128 + arow;
    bool ok = row < NROWS;
    auto srcOf = [&](int c) -> const float* {
        if (L0F) return (c == 0) ? (xin + ((size_t)(row & 1) * NV + (row >> 1)) * 64)
                                 : (d_z0 + (size_t)row * 64);
        else     return (c < 2) ? (d_out0 + (size_t)row * 128 + c * 64)
                                : (d_z1 + (size_t)row * 128 + (c - 2) * 64);
    };
    float4 pre[4];
    auto ldA = [&](int c) {           // prefetch first half of this thread's span
        const float* src = srcOf(c);
#pragma unroll
        for (int j = 0; j < 4; j++)
            pre[j] = ok ? *(const float4*)(src + kq + 4 * j) : make_float4(0.f, 0.f, 0.f, 0.f);
    };
    auto stA = [&](int c) {           // load second half + convert both to fp16 hi/lo
        const float* src = srcOf(c);
        float4 tail[4];
#pragma unroll
        for (int j = 0; j < 4; j++)
            tail[j] = ok ? *(const float4*)(src + kq + 16 + 4 * j) : make_float4(0.f, 0.f, 0.f, 0.f);
        unsigned short* ahi = (unsigned short*)(sm + SA);
        unsigned short* alo = ahi + 128 * BST;
#pragma unroll
        for (int j = 0; j < 4; j++) {
            int kk = kq + 4 * j;
            float4 v = pre[j];
            *(uint2*)(ahi + arow * BST + kk) = make_uint2(pkh(v.x, v.y), pkh(v.z, v.w));
            *(uint2*)(alo + arow * BST + kk) = make_uint2(pkh(v.x - hhi(v.x), v.y - hhi(v.y)),
                                                         pkh(v.z - hhi(v.z), v.w - hhi(v.w)));
        }
#pragma unroll
        for (int j = 0; j < 4; j++) {
            int kk = kq + 16 + 4 * j;
            float4 v = tail[j];
            *(uint2*)(ahi + arow * BST + kk) = make_uint2(pkh(v.x, v.y), pkh(v.z, v.w));
            *(uint2*)(alo + arow * BST + kk) = make_uint2(pkh(v.x - hhi(v.x), v.y - hhi(v.y)),
                                                         pkh(v.z - hhi(v.z), v.w - hhi(v.w)));
        }
    };

    float acc[2][8][4];
#pragma unroll
    for (int m = 0; m < 2; m++)
#pragma unroll
        for (int nf = 0; nf < 8; nf++)
#pragma unroll
            for (int q = 0; q < 4; q++) acc[m][nf][q] = 0.f;

    int a_r = wm + (lane & 15);
    int a_k = (lane >> 4) << 3;
    int b_n = wn + (lane & 7) + ((lane >> 4) << 3);
    int b_k = ((lane >> 3) & 1) << 3;

    auto compute = [&](int s) {
        uint32_t aB = smb + SA;
        uint32_t bB = smb + SB + s * 18432;
#pragma unroll
        for (int ks = 0; ks < 4; ks++) {
            int k0 = ks * 16;
            uint32_t ahi[2][4], alo[2][4];
#pragma unroll
            for (int m = 0; m < 2; m++) {
                uint32_t ad = aB + (uint32_t)(((a_r + m * 16) * BST + k0 + a_k) * 2);
                ldmat4(ahi[m], ad);
                ldmat4(alo[m], ad + 128 * BST * 2);
            }
            uint32_t bhi[8][2];
#pragma unroll
            for (int g = 0; g < 4; g++) {
                uint32_t bd = bB + (uint32_t)(((b_n + g * 16) * BST + k0 + b_k) * 2);
                uint32_t t[4];
                ldmat4(t, bd);
                bhi[2 * g][0] = t[0]; bhi[2 * g][1] = t[1];
                bhi[2 * g + 1][0] = t[2]; bhi[2 * g + 1][1] = t[3];
            }
            // 2-pass: Ahi*B then Alo*B (accumulator reuse distance 16)
#pragma unroll
            for (int m = 0; m < 2; m++)
#pragma unroll
                for (int nf = 0; nf < 8; nf++) mma_f16(acc[m][nf], ahi[m], bhi[nf]);
#pragma unroll
            for (int m = 0; m < 2; m++)
#pragma unroll
                for (int nf = 0; nf < 8; nf++) mma_f16(acc[m][nf], alo[m], bhi[nf]);
        }
    };

    // pipeline: B double-buffered via cp.async; A single-buffered with register prefetch
    prefetchB(0, 0);
    ldA(0);
    stA(0);
    if (NC > 1) { prefetchB(1, 1); ldA(1); CPA_WAIT1(); } else { CPA_WAIT0(); }
    __syncthreads();
#pragma unroll
    for (int c = 0; c < NC; c++) {
        compute(c & 1);
        if (c + 1 < NC) {
            __syncthreads();
            stA(c + 1);
            if (c + 2 < NC) { prefetchB(c + 2, c & 1); ldA(c + 2); CPA_WAIT1(); }
            else CPA_WAIT0();
            __syncthreads();
        }
    }

    // epilogue
    float* outp = L0F ? d_out0 : d_out1;
    const float* sbias = (const float*)sm;
#pragma unroll
    for (int m = 0; m < 2; m++) {
        int r0 = tile * 128 + wm + m * 16 + (lane >> 2);
#pragma unroll
        for (int nf = 0; nf < 8; nf++) {
            int col = wn + nf * 8 + (lane & 3) * 2;
            float bx = sbias[col], by = sbias[col + 1];
            float o0 = acc[m][nf][0] + bx, o1 = acc[m][nf][1] + by;
            float o2 = acc[m][nf][2] + bx, o3 = acc[m][nf][3] + by;
            if (L0F) {
                o0 = (o0 >= 0.f) ? o0 : 0.2f * o0;
                o1 = (o1 >= 0.f) ? o1 : 0.2f * o1;
                o2 = (o2 >= 0.f) ? o2 : 0.2f * o2;
                o3 = (o3 >= 0.f) ? o3 : 0.2f * o3;
            }
            if (r0 < NROWS)     *(float2*)(outp + (size_t)r0 * 128 + col)       = make_float2(o0, o1);
            if (r0 + 8 < NROWS) *(float2*)(outp + (size_t)(r0 + 8) * 128 + col) = make_float2(o2, o3);
        }
    }
}

// ---------------- final: pool(out1) + (pool(x) @ W_res + sw * b_res) ----------------
__global__ void __launch_bounds__(256) k_final(const float* __restrict__ x,
                                               const int* __restrict__ asgnIdx,
                                               const float* __restrict__ asgnVal,
                                               const float* __restrict__ Wres,
                                               const float* __restrict__ bres,
                                               float* __restrict__ out) {
    __shared__ float xps[4][64];
    if (blockIdx.x == 0 && threadIdx.x == 0) { d_barA = 0; d_barB = 0; }  // reset for next graph replay
    int sub = threadIdx.x >> 6;
    int p = threadIdx.x & 63;
    int r = blockIdx.x * 4 + sub;
    bool ok = r < 2 * CN;
    int c = r >> 1, b = r & 1;
    const int* fine = asgnIdx + NV;
    float sw = 0.f;
    float2 p1 = make_float2(0.f, 0.f);
    if (ok) {
        int i0 = 4 * c;
        float a = 0.f;
#pragma unroll
        for (int j = 0; j < 4; j++) {
            int f = fine[i0 + j];
            float w = asgnVal[i0 + j];
            a = fmaf(w, x[((size_t)b * NV + f) * 64 + p], a);
            sw += w;
            float2 o1 = *(const float2*)(&d_out1[((size_t)(2 * f + b)) * 128 + 2 * p]);
            p1.x = fmaf(w, o1.x, p1.x);
            p1.y = fmaf(w, o1.y, p1.y);
        }
        xps[sub][p] = a;
    }
    __syncthreads();
    if (ok) {
        float2 br = *(const float2*)(bres + 2 * p);
        float accx = p1.x + sw * br.x;
        float accy = p1.y + sw * br.y;
#pragma unroll 8
        for (int k = 0; k < 64; k++) {
            float xk = xps[sub][k];
            float2 w2 = *(const float2*)(Wres + k * 128 + 2 * p);
            accx = fmaf(xk, w2.x, accx);
            accy = fmaf(xk, w2.y, accy);
        }
        *(float2*)(out + ((size_t)b * CN + c) * 128 + 2 * p) = make_float2(accx, accy);
    }
}

// ---------------- launch ----------------
extern "C" void kernel_launch(void* const* d_in, const int* in_sizes, int n_in,
                              void* d_out, int out_size) {
    const float* x       = (const float*)d_in[0];
    const float* adjVal  = (const float*)d_in[1];
    const float* edgeOne = (const float*)d_in[2];
    const int*   E_start = (const int*)d_in[3];
    const int*   E_end   = (const int*)d_in[4];
    const int*   asgnIdx = (const int*)d_in[5];
    const float* asgnVal = (const float*)d_in[6];
    const float* W_res   = (const float*)d_in[7];
    const float* b_res   = (const float*)d_in[8];
    const float* W0s     = (const float*)d_in[9];
    const float* W0n     = (const float*)d_in[10];
    const float* b0      = (const float*)d_in[11];
    const float* W1s     = (const float*)d_in[12];
    const float* W1n     = (const float*)d_in[13];
    const float* b1      = (const float*)d_in[14];
    float* out = (float*)d_out;

    const int smG = 1024 + 36864 + 2 * 18432;   // 74752 -> 2 CTAs/SM, more L1 carveout
    cudaFuncSetAttribute(k_gemm<2, true>,  cudaFuncAttributeMaxDynamicSharedMemorySize, smG);
    cudaFuncSetAttribute(k_gemm<4, false>, cudaFuncAttributeMaxDynamicSharedMemorySize, smG);

    k_prep<<<PPB, 256>>>(W0s, W0n, W1s, W1n, E_start, edgeOne);    // 0 (zero + Wimg + hist)
    k_scanfill<<<SFB, 512>>>(E_start, E_end, adjVal);              // 1
    k_gather64<<<NV / 8, 256>>>(x);                                // 2
    k_gemm<2, true><<<NTILES, 256, smG>>>(x, b0);                  // 3 <- ncu capture slot
    k_gather128<<<NV / 8, 256>>>();                                // 4
    k_gemm<4, false><<<NTILES, 256, smG>>>(x, b1);                 // 5
    k_final<<<(2 * CN + 3) / 4, 256>>>(x, asgnIdx, asgnVal, W_res, b_res, out); // 6
}

// round 10
// speedup vs baseline: 1.9565x; 1.2913x over previous
#include <cuda_runtime.h>
#include <cuda_fp16.h>
#include <cstdint>

#define NV 50000
#define NE 400000
#define CN 12500
#define NROWS 100000
#define NROWSP 100096   /* 782 * 128 */
#define NTILES 782
#define BST 72          /* fp16 elems per smem row (64 data + 8 pad) */
#define SFB 98
#define PPB 148

// ---------------- scratch (static device memory) ----------------
__device__ int   d_barA;
__device__ int   d_barB;
__device__ int   d_degcnt[NV];
__device__ float d_degF[NV];
__device__ int   d_rowptr[NV + 1];
__device__ int   d_cursor[NV];
__device__ float d_deginv[NV];
__device__ int   d_blocksums[128];
__device__ int2  d_sorted[NE];                         // (end, val bits)
__device__ float d_out1[(size_t)NV * 256];             // fp32 for k_final
// fp16 feature images, row r = 2v+b
__device__ unsigned short d_h0x[(size_t)NROWSP * 64];  // x
__device__ unsigned short d_h0z[(size_t)NROWSP * 64];  // z0
__device__ unsigned short d_h1 [(size_t)NROWSP * 128]; // out0
__device__ unsigned short d_h1z[(size_t)NROWSP * 128]; // z1
// fp16 weight images: [chunk][n][BST]
__device__ unsigned short d_Wimg0[2 * 128 * BST];
__device__ unsigned short d_Wimg1[4 * 128 * BST];

// ---------------- helpers ----------------
__device__ __forceinline__ uint32_t smem_u32(const void* p) {
    uint32_t a;
    asm("{ .reg .u64 t; cvta.to.shared.u64 t, %1; cvt.u32.u64 %0, t; }" : "=r"(a) : "l"(p));
    return a;
}
__device__ __forceinline__ void ldmat4(uint32_t* r, uint32_t addr) {
    asm volatile("ldmatrix.sync.aligned.m8n8.x4.shared.b16 {%0,%1,%2,%3}, [%4];"
                 : "=r"(r[0]), "=r"(r[1]), "=r"(r[2]), "=r"(r[3]) : "r"(addr));
}
__device__ __forceinline__ void mma_f16(float* d, const uint32_t* a, const uint32_t* b) {
    asm volatile("mma.sync.aligned.m16n8k16.row.col.f32.f16.f16.f32 "
                 "{%0,%1,%2,%3}, {%4,%5,%6,%7}, {%8,%9}, {%0,%1,%2,%3};"
                 : "+f"(d[0]), "+f"(d[1]), "+f"(d[2]), "+f"(d[3])
                 : "r"(a[0]), "r"(a[1]), "r"(a[2]), "r"(a[3]), "r"(b[0]), "r"(b[1]));
}
__device__ __forceinline__ void cpa16(uint32_t dst, const void* src) {
    asm volatile("cp.async.cg.shared.global [%0], [%1], 16;" :: "r"(dst), "l"(src) : "memory");
}
#define CPA_COMMIT() asm volatile("cp.async.commit_group;" ::: "memory")
#define CPA_WAIT0()  asm volatile("cp.async.wait_group 0;" ::: "memory")
#define CPA_WAIT1()  asm volatile("cp.async.wait_group 1;" ::: "memory")

__device__ __forceinline__ unsigned short hfb(float x) {
    return __half_as_ushort(__float2half_rn(x));
}
__device__ __forceinline__ uint32_t pkh(float a, float b) {
    return (uint32_t)hfb(a) | ((uint32_t)hfb(b) << 16);
}
__device__ __forceinline__ float2 h2f(uint32_t u) {
    __half2 h = *reinterpret_cast<const __half2*>(&u);
    return __half22float2(h);
}

// software grid barrier (all blocks co-resident by construction)
__device__ __forceinline__ void gbar(int* ctr, int target) {
    __syncthreads();
    __threadfence();
    if (threadIdx.x == 0) {
        atomicAdd(ctr, 1);
        while (atomicAdd(ctr, 0) < target) { }
    }
    __syncthreads();
    __threadfence();
}

// ---------------- k_prep: zero + fp16 weight images + x conversion + (gbar) + hist ----------------
__global__ void __launch_bounds__(256) k_prep(const float* __restrict__ W0s, const float* __restrict__ W0n,
                                              const float* __restrict__ W1s, const float* __restrict__ W1n,
                                              const float* __restrict__ x,
                                              const int* __restrict__ Es, const float* __restrict__ one) {
    int gt = blockIdx.x * blockDim.x + threadIdx.x;
    const int stride = PPB * 256;
    for (int i = gt; i < NV; i += stride) {
        d_degcnt[i] = 0; d_degF[i] = 0.f; d_cursor[i] = 0;
    }
    // weight images
    for (int it = gt; it < 49152; it += stride) {
        bool isL1 = it >= 16384;
        int loc = isL1 ? (it - 16384) : it;
        int c = loc >> 13;
        int rem = loc & 8191;
        int n = rem >> 6;
        int kl = rem & 63;
        int k = c * 64 + kl;
        float v;
        if (isL1) v = (k < 128) ? W1s[(size_t)k * 128 + n] : W1n[(size_t)(k - 128) * 128 + n];
        else      v = (k < 64)  ? W0s[(size_t)k * 128 + n] : W0n[(size_t)(k - 64) * 128 + n];
        unsigned short* img = isL1 ? d_Wimg1 : d_Wimg0;
        img[(size_t)(c * 128 + n) * BST + kl] = hfb(v);
    }
    // x -> fp16 image (row r = 2v+b)
    for (int it = gt; it < NROWS * 8; it += stride) {
        int row = it >> 3, k8 = (it & 7) * 8;
        const float* src = x + ((size_t)(row & 1) * NV + (row >> 1)) * 64 + k8;
        float4 a = *(const float4*)src;
        float4 b = *(const float4*)(src + 4);
        uint4 o = make_uint4(pkh(a.x, a.y), pkh(a.z, a.w), pkh(b.x, b.y), pkh(b.z, b.w));
        *(uint4*)(d_h0x + (size_t)row * 64 + k8) = o;
    }
    gbar(&d_barA, PPB);
    // histogram
    for (int e = gt; e < NE; e += stride) {
        int s = Es[e];
        atomicAdd(&d_degcnt[s], 1);
        atomicAdd(&d_degF[s], one[e]);
    }
}

// ---------------- k_scanfill: scan -> fixup -> CSR fill (grid barriers) ----------------
__global__ void __launch_bounds__(512) k_scanfill(const int* __restrict__ Es,
                                                  const int* __restrict__ Ee,
                                                  const float* __restrict__ adj) {
    __shared__ int s[512];
    const int NT = SFB * 512;
    int tid = threadIdx.x;
    int gt = blockIdx.x * 512 + tid;

    int val = (gt < NV) ? d_degcnt[gt] : 0;
    s[tid] = val;
    __syncthreads();
    for (int off = 1; off < 512; off <<= 1) {
        int t = (tid >= off) ? s[tid - off] : 0;
        __syncthreads();
        s[tid] += t;
        __syncthreads();
    }
    if (gt < NV) d_rowptr[gt + 1] = s[tid];
    if (tid == 511) d_blocksums[blockIdx.x] = s[511];
    gbar(&d_barB, SFB);

    {
        s[tid] = (tid < SFB) ? d_blocksums[tid] : 0;
        __syncthreads();
        for (int off = 1; off < 512; off <<= 1) {
            int u = (tid >= off) ? s[tid - off] : 0;
            __syncthreads();
            s[tid] += u;
            __syncthreads();
        }
        int boff = (blockIdx.x > 0) ? s[blockIdx.x - 1] : 0;
        if (gt < NV) {
            d_rowptr[gt + 1] += boff;
            d_deginv[gt] = 1.0f / fmaxf(d_degF[gt], 1.0f);
        }
        if (gt == 0) d_rowptr[0] = 0;
    }
    gbar(&d_barB, 2 * SFB);

    for (int e = gt; e < NE; e += NT) {
        int src = Es[e];
        int p = atomicAdd(&d_cursor[src], 1);
        d_sorted[d_rowptr[src] + p] = make_int2(Ee[e], __float_as_int(adj[e]));
    }
}

// ---------------- gather64: warp/node, fp16 reads, fp16 z0 write ----------------
__global__ void __launch_bounds__(256) k_gather64() {
    int v = blockIdx.x * 8 + (threadIdx.x >> 5);
    int lane = threadIdx.x & 31;
    int b = lane >> 4, k = (lane & 15) * 4;
    int i = d_rowptr[v], end = d_rowptr[v + 1];
    float4 acc = make_float4(0.f, 0.f, 0.f, 0.f);
    for (; i + 2 <= end; i += 2) {
        int2 e0 = d_sorted[i];
        int2 e1 = d_sorted[i + 1];
        float w0 = __int_as_float(e0.y), w1 = __int_as_float(e1.y);
        uint2 q0 = *(const uint2*)(d_h0x + ((size_t)e0.x * 2 + b) * 64 + k);
        uint2 q1 = *(const uint2*)(d_h0x + ((size_t)e1.x * 2 + b) * 64 + k);
        float2 f0a = h2f(q0.x), f0b = h2f(q0.y);
        float2 f1a = h2f(q1.x), f1b = h2f(q1.y);
        acc.x = fmaf(w0, f0a.x, fmaf(w1, f1a.x, acc.x));
        acc.y = fmaf(w0, f0a.y, fmaf(w1, f1a.y, acc.y));
        acc.z = fmaf(w0, f0b.x, fmaf(w1, f1b.x, acc.z));
        acc.w = fmaf(w0, f0b.y, fmaf(w1, f1b.y, acc.w));
    }
    if (i < end) {
        int2 e0 = d_sorted[i];
        float w0 = __int_as_float(e0.y);
        uint2 q0 = *(const uint2*)(d_h0x + ((size_t)e0.x * 2 + b) * 64 + k);
        float2 f0a = h2f(q0.x), f0b = h2f(q0.y);
        acc.x = fmaf(w0, f0a.x, acc.x);
        acc.y = fmaf(w0, f0a.y, acc.y);
        acc.z = fmaf(w0, f0b.x, acc.z);
        acc.w = fmaf(w0, f0b.y, acc.w);
    }
    float di = d_deginv[v];
    acc.x *= di; acc.y *= di; acc.z *= di; acc.w *= di;
    *(uint2*)(d_h0z + ((size_t)v * 2 + b) * 64 + k) = make_uint2(pkh(acc.x, acc.y), pkh(acc.z, acc.w));
}

// ---------------- gather128: warp/node, fp16 out0 reads (16B/lane), fp16 z1 write ----------------
__global__ void __launch_bounds__(256) k_gather128() {
    int v = blockIdx.x * 8 + (threadIdx.x >> 5);
    int lane = threadIdx.x & 31;
    int fo = lane * 8;                 // half index in [0,256): covers (b, feat) pairs
    int i = d_rowptr[v], end = d_rowptr[v + 1];
    float a[8];
#pragma unroll
    for (int j = 0; j < 8; j++) a[j] = 0.f;
    for (; i + 2 <= end; i += 2) {
        int2 e0 = d_sorted[i];
        int2 e1 = d_sorted[i + 1];
        float w0 = __int_as_float(e0.y), w1 = __int_as_float(e1.y);
        uint4 q0 = *(const uint4*)(d_h1 + (size_t)e0.x * 256 + fo);
        uint4 q1 = *(const uint4*)(d_h1 + (size_t)e1.x * 256 + fo);
        float2 f;
        f = h2f(q0.x); a[0] = fmaf(w0, f.x, a[0]); a[1] = fmaf(w0, f.y, a[1]);
        f = h2f(q0.y); a[2] = fmaf(w0, f.x, a[2]); a[3] = fmaf(w0, f.y, a[3]);
        f = h2f(q0.z); a[4] = fmaf(w0, f.x, a[4]); a[5] = fmaf(w0, f.y, a[5]);
        f = h2f(q0.w); a[6] = fmaf(w0, f.x, a[6]); a[7] = fmaf(w0, f.y, a[7]);
        f = h2f(q1.x); a[0] = fmaf(w1, f.x, a[0]); a[1] = fmaf(w1, f.y, a[1]);
        f = h2f(q1.y); a[2] = fmaf(w1, f.x, a[2]); a[3] = fmaf(w1, f.y, a[3]);
        f = h2f(q1.z); a[4] = fmaf(w1, f.x, a[4]); a[5] = fmaf(w1, f.y, a[5]);
        f = h2f(q1.w); a[6] = fmaf(w1, f.x, a[6]); a[7] = fmaf(w1, f.y, a[7]);
    }
    if (i < end) {
        int2 e0 = d_sorted[i];
        float w0 = __int_as_float(e0.y);
        uint4 q0 = *(const uint4*)(d_h1 + (size_t)e0.x * 256 + fo);
        float2 f;
        f = h2f(q0.x); a[0] = fmaf(w0, f.x, a[0]); a[1] = fmaf(w0, f.y, a[1]);
        f = h2f(q0.y); a[2] = fmaf(w0, f.x, a[2]); a[3] = fmaf(w0, f.y, a[3]);
        f = h2f(q0.z); a[4] = fmaf(w0, f.x, a[4]); a[5] = fmaf(w0, f.y, a[5]);
        f = h2f(q0.w); a[6] = fmaf(w0, f.x, a[6]); a[7] = fmaf(w0, f.y, a[7]);
    }
    float di = d_deginv[v];
#pragma unroll
    for (int j = 0; j < 8; j++) a[j] *= di;
    int rz = 2 * v + (lane >> 4);
    int f0i = (lane & 15) * 8;
    *(uint4*)(d_h1z + (size_t)rz * 128 + f0i) =
        make_uint4(pkh(a[0], a[1]), pkh(a[2], a[3]), pkh(a[4], a[5]), pkh(a[6], a[7]));
}

// ---------------- tensor-core GEMM: pure fp16, dual cp.async 2-stage pipeline ----------------
// CTA 128x128, chunk-64 K. smem: bias 1024 + A stages 2x18432 + B stages 2x18432 = 74752.
template <int NC, bool L0F>
__global__ void __launch_bounds__(256, 2) k_gemm(const float* __restrict__ bias) {
    extern __shared__ unsigned char sm[];
    const int SA = 1024;
    const int SB = 1024 + 2 * 18432;
    int tid = threadIdx.x;
    int wid = tid >> 5, lane = tid & 31;
    int tile = blockIdx.x;
    int wm = (wid & 3) * 32, wn = (wid >> 2) * 64;
    uint32_t smb = smem_u32(sm);
    const unsigned short* wimg = L0F ? d_Wimg0 : d_Wimg1;

    auto Abase = [&](int c, int rowl) -> const unsigned short* {
        size_t r = (size_t)(tile * 128 + rowl);
        if (L0F) return (c == 0 ? d_h0x : d_h0z) + r * 64;
        else     return (c < 2 ? d_h1 + c * 64 : d_h1z + (c - 2) * 64) + r * 128;
    };

    auto prefetch = [&](int c, int s) {
        // A: 128 rows x 128B = 1024 segs of 16B
#pragma unroll
        for (int i = 0; i < 4; i++) {
            int seg = tid + i * 256;
            int rowl = seg >> 3, q = seg & 7;
            cpa16(smb + SA + s * 18432 + rowl * 144 + q * 16, Abase(c, rowl) + q * 8);
        }
        // B: 18432B contiguous = 1152 segs
        const unsigned char* bsrc = (const unsigned char*)(wimg + (size_t)c * (128 * BST));
#pragma unroll
        for (int i = 0; i < 5; i++) {
            int seg = tid + i * 256;
            if (seg < 1152) cpa16(smb + SB + s * 18432 + seg * 16, bsrc + seg * 16);
        }
        CPA_COMMIT();
    };

    if (tid < 128) ((float*)sm)[tid] = bias[tid];

    float acc[2][8][4];
#pragma unroll
    for (int m = 0; m < 2; m++)
#pragma unroll
        for (int nf = 0; nf < 8; nf++)
#pragma unroll
            for (int q = 0; q < 4; q++) acc[m][nf][q] = 0.f;

    int a_r = wm + (lane & 15);
    int a_k = (lane >> 4) << 3;
    int b_n = wn + (lane & 7) + ((lane >> 4) << 3);
    int b_k = ((lane >> 3) & 1) << 3;

    auto compute = [&](int s) {
        uint32_t aB = smb + SA + s * 18432;
        uint32_t bB = smb + SB + s * 18432;
#pragma unroll
        for (int ks = 0; ks < 4; ks++) {
            int k0 = ks * 16;
            uint32_t ah[2][4];
#pragma unroll
            for (int m = 0; m < 2; m++)
                ldmat4(ah[m], aB + (uint32_t)(((a_r + m * 16) * BST + k0 + a_k) * 2));
            uint32_t bh[8][2];
#pragma unroll
            for (int g = 0; g < 4; g++) {
                uint32_t t[4];
                ldmat4(t, bB + (uint32_t)(((b_n + g * 16) * BST + k0 + b_k) * 2));
                bh[2 * g][0] = t[0]; bh[2 * g][1] = t[1];
                bh[2 * g + 1][0] = t[2]; bh[2 * g + 1][1] = t[3];
            }
#pragma unroll
            for (int m = 0; m < 2; m++)
#pragma unroll
                for (int nf = 0; nf < 8; nf++) mma_f16(acc[m][nf], ah[m], bh[nf]);
        }
    };

    prefetch(0, 0);
    if (NC > 1) prefetch(1, 1);
#pragma unroll
    for (int c = 0; c < NC; c++) {
        if (c < NC - 1) { CPA_WAIT1(); } else { CPA_WAIT0(); }
        __syncthreads();
        compute(c & 1);
        __syncthreads();
        if (c + 2 < NC) prefetch(c + 2, c & 1);
    }

    // epilogue
    const float* sbias = (const float*)sm;
#pragma unroll
    for (int m = 0; m < 2; m++) {
        int r0 = tile * 128 + wm + m * 16 + (lane >> 2);
#pragma unroll
        for (int nf = 0; nf < 8; nf++) {
            int col = wn + nf * 8 + (lane & 3) * 2;
            float bx = sbias[col], by = sbias[col + 1];
            float o0 = acc[m][nf][0] + bx, o1 = acc[m][nf][1] + by;
            float o2 = acc[m][nf][2] + bx, o3 = acc[m][nf][3] + by;
            if (L0F) {
                o0 = (o0 >= 0.f) ? o0 : 0.2f * o0;
                o1 = (o1 >= 0.f) ? o1 : 0.2f * o1;
                o2 = (o2 >= 0.f) ? o2 : 0.2f * o2;
                o3 = (o3 >= 0.f) ? o3 : 0.2f * o3;
                if (r0 < NROWS)
                    *(uint32_t*)(d_h1 + (size_t)r0 * 128 + col) = pkh(o0, o1);
                if (r0 + 8 < NROWS)
                    *(uint32_t*)(d_h1 + (size_t)(r0 + 8) * 128 + col) = pkh(o2, o3);
            } else {
                if (r0 < NROWS)     *(float2*)(d_out1 + (size_t)r0 * 128 + col)       = make_float2(o0, o1);
                if (r0 + 8 < NROWS) *(float2*)(d_out1 + (size_t)(r0 + 8) * 128 + col) = make_float2(o2, o3);
            }
        }
    }
}

// ---------------- final: pool(out1) + (pool(x) @ W_res + sw * b_res) ----------------
__global__ void __launch_bounds__(256) k_final(const float* __restrict__ x,
                                               const int* __restrict__ asgnIdx,
                                               const float* __restrict__ asgnVal,
                                               const float* __restrict__ Wres,
                                               const float* __restrict__ bres,
                                               float* __restrict__ out) {
    __shared__ float xps[4][64];
    if (blockIdx.x == 0 && threadIdx.x == 0) { d_barA = 0; d_barB = 0; }  // reset for next replay
    int sub = threadIdx.x >> 6;
    int p = threadIdx.x & 63;
    int r = blockIdx.x * 4 + sub;
    bool ok = r < 2 * CN;
    int c = r >> 1, b = r & 1;
    const int* fine = asgnIdx + NV;
    float sw = 0.f;
    float2 p1 = make_float2(0.f, 0.f);
    if (ok) {
        int i0 = 4 * c;
        float a = 0.f;
#pragma unroll
        for (int j = 0; j < 4; j++) {
            int f = fine[i0 + j];
            float w = asgnVal[i0 + j];
            a = fmaf(w, x[((size_t)b * NV + f) * 64 + p], a);
            sw += w;
            float2 o1 = *(const float2*)(&d_out1[((size_t)(2 * f + b)) * 128 + 2 * p]);
            p1.x = fmaf(w, o1.x, p1.x);
            p1.y = fmaf(w, o1.y, p1.y);
        }
        xps[sub][p] = a;
    }
    __syncthreads();
    if (ok) {
        float2 br = *(const float2*)(bres + 2 * p);
        float accx = p1.x + sw * br.x;
        float accy = p1.y + sw * br.y;
#pragma unroll 8
        for (int k = 0; k < 64; k++) {
            float xk = xps[sub][k];
            float2 w2 = *(const float2*)(Wres + k * 128 + 2 * p);
            accx = fmaf(xk, w2.x, accx);
            accy = fmaf(xk, w2.y, accy);
        }
        *(float2*)(out + ((size_t)b * CN + c) * 128 + 2 * p) = make_float2(accx, accy);
    }
}

// ---------------- launch ----------------
extern "C" void kernel_launch(void* const* d_in, const int* in_sizes, int n_in,
                              void* d_out, int out_size) {
    const float* x       = (const float*)d_in[0];
    const float* adjVal  = (const float*)d_in[1];
    const float* edgeOne = (const float*)d_in[2];
    const int*   E_start = (const int*)d_in[3];
    const int*   E_end   = (const int*)d_in[4];
    const int*   asgnIdx = (const int*)d_in[5];
    const float* asgnVal = (const float*)d_in[6];
    const float* W_res   = (const float*)d_in[7];
    const float* b_res   = (const float*)d_in[8];
    const float* W0s     = (const float*)d_in[9];
    const float* W0n     = (const float*)d_in[10];
    const float* b0      = (const float*)d_in[11];
    const float* W1s     = (const float*)d_in[12];
    const float* W1n     = (const float*)d_in[13];
    const float* b1      = (const float*)d_in[14];
    float* out = (float*)d_out;

    const int smG = 1024 + 4 * 18432;   // 74752 -> 2 CTAs/SM
    cudaFuncSetAttribute(k_gemm<2, true>,  cudaFuncAttributeMaxDynamicSharedMemorySize, smG);
    cudaFuncSetAttribute(k_gemm<4, false>, cudaFuncAttributeMaxDynamicSharedMemorySize, smG);

    k_prep<<<PPB, 256>>>(W0s, W0n, W1s, W1n, x, E_start, edgeOne); // 0 (zero + Wimg + x->fp16 + hist)
    k_scanfill<<<SFB, 512>>>(E_start, E_end, adjVal);              // 1
    k_gather64<<<NV / 8, 256>>>();                                 // 2
    k_gemm<2, true><<<NTILES, 256, smG>>>(b0);                     // 3 <- ncu capture slot
    k_gather128<<<NV / 8, 256>>>();                                // 4
    k_gemm<4, false><<<NTILES, 256, smG>>>(b1);                    // 5
    k_final<<<(2 * CN + 3) / 4, 256>>>(x, asgnIdx, asgnVal, W_res, b_res, out); // 6
}

// round 11
// speedup vs baseline: 2.0243x; 1.0347x over previous
#include <cuda_runtime.h>
#include <cuda_fp16.h>
#include <cstdint>

#define NV 50000
#define NE 400000
#define CN 12500
#define NROWS 100000
#define NROWSP 100096   /* 782 * 128 */
#define NTILES 782
#define SFB 98
#define PPB 148
#define GGRID 296       /* persistent GEMM grid: 2 CTAs/SM */

// ---------------- scratch (static device memory) ----------------
__device__ int   d_barA;
__device__ int   d_barB;
__device__ int   d_degcnt[NV];
__device__ float d_degF[NV];
__device__ int   d_rowptr[NV + 1];
__device__ int   d_cursor[NV];
__device__ float d_deginv[NV];
__device__ int   d_blocksums[128];
__device__ int2  d_sorted[NE];                         // (end, val bits)
// fp16 feature images, row r = 2v+b
__device__ unsigned short d_h0x[(size_t)NROWSP * 64];  // x
__device__ unsigned short d_h0z[(size_t)NROWSP * 64];  // z0
__device__ unsigned short d_h1 [(size_t)NROWSP * 128]; // out0, then out1 (in-place)
__device__ unsigned short d_h1z[(size_t)NROWSP * 128]; // z1
// fp16 weight images, XOR-swizzled smem layout: [chunk][n][64] with 16B-chunk swizzle
__device__ unsigned short d_Wimg0[2 * 128 * 64];
__device__ unsigned short d_Wimg1[4 * 128 * 64];

// ---------------- helpers ----------------
__device__ __forceinline__ uint32_t smem_u32(const void* p) {
    uint32_t a;
    asm("{ .reg .u64 t; cvta.to.shared.u64 t, %1; cvt.u32.u64 %0, t; }" : "=r"(a) : "l"(p));
    return a;
}
__device__ __forceinline__ void ldmat4(uint32_t* r, uint32_t addr) {
    asm volatile("ldmatrix.sync.aligned.m8n8.x4.shared.b16 {%0,%1,%2,%3}, [%4];"
                 : "=r"(r[0]), "=r"(r[1]), "=r"(r[2]), "=r"(r[3]) : "r"(addr));
}
__device__ __forceinline__ void mma_f16(float* d, const uint32_t* a, const uint32_t* b) {
    asm volatile("mma.sync.aligned.m16n8k16.row.col.f32.f16.f16.f32 "
                 "{%0,%1,%2,%3}, {%4,%5,%6,%7}, {%8,%9}, {%0,%1,%2,%3};"
                 : "+f"(d[0]), "+f"(d[1]), "+f"(d[2]), "+f"(d[3])
                 : "r"(a[0]), "r"(a[1]), "r"(a[2]), "r"(a[3]), "r"(b[0]), "r"(b[1]));
}
__device__ __forceinline__ void cpa16(uint32_t dst, const void* src) {
    asm volatile("cp.async.cg.shared.global [%0], [%1], 16;" :: "r"(dst), "l"(src) : "memory");
}
#define CPA_COMMIT() asm volatile("cp.async.commit_group;" ::: "memory")
#define CPA_WAIT1()  asm volatile("cp.async.wait_group 1;" ::: "memory")

__device__ __forceinline__ unsigned short hfb(float x) {
    return __half_as_ushort(__float2half_rn(x));
}
__device__ __forceinline__ uint32_t pkh(float a, float b) {
    return (uint32_t)hfb(a) | ((uint32_t)hfb(b) << 16);
}
__device__ __forceinline__ float2 h2f(uint32_t u) {
    __half2 h = *reinterpret_cast<const __half2*>(&u);
    return __half22float2(h);
}

// software grid barrier (all blocks co-resident by construction)
__device__ __forceinline__ void gbar(int* ctr, int target) {
    __syncthreads();
    __threadfence();
    if (threadIdx.x == 0) {
        atomicAdd(ctr, 1);
        while (atomicAdd(ctr, 0) < target) { }
    }
    __syncthreads();
    __threadfence();
}

// ---------------- k_prep: zero + swizzled fp16 weight images + x conversion + hist ----------------
__global__ void __launch_bounds__(256) k_prep(const float* __restrict__ W0s, const float* __restrict__ W0n,
                                              const float* __restrict__ W1s, const float* __restrict__ W1n,
                                              const float* __restrict__ x,
                                              const int* __restrict__ Es, const float* __restrict__ one) {
    int gt = blockIdx.x * blockDim.x + threadIdx.x;
    const int stride = PPB * 256;
    for (int i = gt; i < NV; i += stride) {
        d_degcnt[i] = 0; d_degF[i] = 0.f; d_cursor[i] = 0;
    }
    // weight images (XOR-swizzled rows of 128B = 8 x 16B chunks)
    for (int it = gt; it < 49152; it += stride) {
        bool isL1 = it >= 16384;
        int loc = isL1 ? (it - 16384) : it;
        int c = loc >> 13;
        int rem = loc & 8191;
        int n = rem >> 6;
        int kl = rem & 63;
        int k = c * 64 + kl;
        float v;
        if (isL1) v = (k < 128) ? W1s[(size_t)k * 128 + n] : W1n[(size_t)(k - 128) * 128 + n];
        else      v = (k < 64)  ? W0s[(size_t)k * 128 + n] : W0n[(size_t)(k - 64) * 128 + n];
        unsigned short* img = isL1 ? d_Wimg1 : d_Wimg0;
        int q = kl >> 3;
        img[(size_t)(c * 128 + n) * 64 + ((q ^ (n & 7)) * 8 + (kl & 7))] = hfb(v);
    }
    // x -> fp16 image (row r = 2v+b)
    for (int it = gt; it < NROWS * 8; it += stride) {
        int row = it >> 3, k8 = (it & 7) * 8;
        const float* src = x + ((size_t)(row & 1) * NV + (row >> 1)) * 64 + k8;
        float4 a = *(const float4*)src;
        float4 b = *(const float4*)(src + 4);
        uint4 o = make_uint4(pkh(a.x, a.y), pkh(a.z, a.w), pkh(b.x, b.y), pkh(b.z, b.w));
        *(uint4*)(d_h0x + (size_t)row * 64 + k8) = o;
    }
    gbar(&d_barA, PPB);
    for (int e = gt; e < NE; e += stride) {
        int s = Es[e];
        atomicAdd(&d_degcnt[s], 1);
        atomicAdd(&d_degF[s], one[e]);
    }
}

// ---------------- k_scanfill: scan -> fixup -> CSR fill (grid barriers) ----------------
__global__ void __launch_bounds__(512) k_scanfill(const int* __restrict__ Es,
                                                  const int* __restrict__ Ee,
                                                  const float* __restrict__ adj) {
    __shared__ int s[512];
    const int NT = SFB * 512;
    int tid = threadIdx.x;
    int gt = blockIdx.x * 512 + tid;

    int val = (gt < NV) ? d_degcnt[gt] : 0;
    s[tid] = val;
    __syncthreads();
    for (int off = 1; off < 512; off <<= 1) {
        int t = (tid >= off) ? s[tid - off] : 0;
        __syncthreads();
        s[tid] += t;
        __syncthreads();
    }
    if (gt < NV) d_rowptr[gt + 1] = s[tid];
    if (tid == 511) d_blocksums[blockIdx.x] = s[511];
    gbar(&d_barB, SFB);

    {
        s[tid] = (tid < SFB) ? d_blocksums[tid] : 0;
        __syncthreads();
        for (int off = 1; off < 512; off <<= 1) {
            int u = (tid >= off) ? s[tid - off] : 0;
            __syncthreads();
            s[tid] += u;
            __syncthreads();
        }
        int boff = (blockIdx.x > 0) ? s[blockIdx.x - 1] : 0;
        if (gt < NV) {
            d_rowptr[gt + 1] += boff;
            d_deginv[gt] = 1.0f / fmaxf(d_degF[gt], 1.0f);
        }
        if (gt == 0) d_rowptr[0] = 0;
    }
    gbar(&d_barB, 2 * SFB);

    for (int e = gt; e < NE; e += NT) {
        int src = Es[e];
        int p = atomicAdd(&d_cursor[src], 1);
        d_sorted[d_rowptr[src] + p] = make_int2(Ee[e], __float_as_int(adj[e]));
    }
}

// ---------------- gather64: warp/node, fp16 reads, fp16 z0 write ----------------
__global__ void __launch_bounds__(256) k_gather64() {
    int v = blockIdx.x * 8 + (threadIdx.x >> 5);
    int lane = threadIdx.x & 31;
    int b = lane >> 4, k = (lane & 15) * 4;
    int i = d_rowptr[v], end = d_rowptr[v + 1];
    float4 acc = make_float4(0.f, 0.f, 0.f, 0.f);
    for (; i + 2 <= end; i += 2) {
        int2 e0 = d_sorted[i];
        int2 e1 = d_sorted[i + 1];
        float w0 = __int_as_float(e0.y), w1 = __int_as_float(e1.y);
        uint2 q0 = *(const uint2*)(d_h0x + ((size_t)e0.x * 2 + b) * 64 + k);
        uint2 q1 = *(const uint2*)(d_h0x + ((size_t)e1.x * 2 + b) * 64 + k);
        float2 f0a = h2f(q0.x), f0b = h2f(q0.y);
        float2 f1a = h2f(q1.x), f1b = h2f(q1.y);
        acc.x = fmaf(w0, f0a.x, fmaf(w1, f1a.x, acc.x));
        acc.y = fmaf(w0, f0a.y, fmaf(w1, f1a.y, acc.y));
        acc.z = fmaf(w0, f0b.x, fmaf(w1, f1b.x, acc.z));
        acc.w = fmaf(w0, f0b.y, fmaf(w1, f1b.y, acc.w));
    }
    if (i < end) {
        int2 e0 = d_sorted[i];
        float w0 = __int_as_float(e0.y);
        uint2 q0 = *(const uint2*)(d_h0x + ((size_t)e0.x * 2 + b) * 64 + k);
        float2 f0a = h2f(q0.x), f0b = h2f(q0.y);
        acc.x = fmaf(w0, f0a.x, acc.x);
        acc.y = fmaf(w0, f0a.y, acc.y);
        acc.z = fmaf(w0, f0b.x, acc.z);
        acc.w = fmaf(w0, f0b.y, acc.w);
    }
    float di = d_deginv[v];
    acc.x *= di; acc.y *= di; acc.z *= di; acc.w *= di;
    *(uint2*)(d_h0z + ((size_t)v * 2 + b) * 64 + k) = make_uint2(pkh(acc.x, acc.y), pkh(acc.z, acc.w));
}

// ---------------- gather128: warp/node, fp16 out0 reads (16B/lane), fp16 z1 write ----------------
__global__ void __launch_bounds__(256) k_gather128() {
    int v = blockIdx.x * 8 + (threadIdx.x >> 5);
    int lane = threadIdx.x & 31;
    int fo = lane * 8;
    int i = d_rowptr[v], end = d_rowptr[v + 1];
    float a[8];
#pragma unroll
    for (int j = 0; j < 8; j++) a[j] = 0.f;
    for (; i + 2 <= end; i += 2) {
        int2 e0 = d_sorted[i];
        int2 e1 = d_sorted[i + 1];
        float w0 = __int_as_float(e0.y), w1 = __int_as_float(e1.y);
        uint4 q0 = *(const uint4*)(d_h1 + (size_t)e0.x * 256 + fo);
        uint4 q1 = *(const uint4*)(d_h1 + (size_t)e1.x * 256 + fo);
        float2 f;
        f = h2f(q0.x); a[0] = fmaf(w0, f.x, a[0]); a[1] = fmaf(w0, f.y, a[1]);
        f = h2f(q0.y); a[2] = fmaf(w0, f.x, a[2]); a[3] = fmaf(w0, f.y, a[3]);
        f = h2f(q0.z); a[4] = fmaf(w0, f.x, a[4]); a[5] = fmaf(w0, f.y, a[5]);
        f = h2f(q0.w); a[6] = fmaf(w0, f.x, a[6]); a[7] = fmaf(w0, f.y, a[7]);
        f = h2f(q1.x); a[0] = fmaf(w1, f.x, a[0]); a[1] = fmaf(w1, f.y, a[1]);
        f = h2f(q1.y); a[2] = fmaf(w1, f.x, a[2]); a[3] = fmaf(w1, f.y, a[3]);
        f = h2f(q1.z); a[4] = fmaf(w1, f.x, a[4]); a[5] = fmaf(w1, f.y, a[5]);
        f = h2f(q1.w); a[6] = fmaf(w1, f.x, a[6]); a[7] = fmaf(w1, f.y, a[7]);
    }
    if (i < end) {
        int2 e0 = d_sorted[i];
        float w0 = __int_as_float(e0.y);
        uint4 q0 = *(const uint4*)(d_h1 + (size_t)e0.x * 256 + fo);
        float2 f;
        f = h2f(q0.x); a[0] = fmaf(w0, f.x, a[0]); a[1] = fmaf(w0, f.y, a[1]);
        f = h2f(q0.y); a[2] = fmaf(w0, f.x, a[2]); a[3] = fmaf(w0, f.y, a[3]);
        f = h2f(q0.z); a[4] = fmaf(w0, f.x, a[4]); a[5] = fmaf(w0, f.y, a[5]);
        f = h2f(q0.w); a[6] = fmaf(w0, f.x, a[6]); a[7] = fmaf(w0, f.y, a[7]);
    }
    float di = d_deginv[v];
#pragma unroll
    for (int j = 0; j < 8; j++) a[j] *= di;
    int rz = 2 * v + (lane >> 4);
    int f0i = (lane & 15) * 8;
    *(uint4*)(d_h1z + (size_t)rz * 128 + f0i) =
        make_uint4(pkh(a[0], a[1]), pkh(a[2], a[3]), pkh(a[4], a[5]), pkh(a[6], a[7]));
}

// ---------------- persistent tensor-core GEMM: resident B, 3-stage A ring, XOR swizzle ----------------
// smem: [0,1024) bias; [1024) A ring 3x16384; [50176) B resident NC x 16384.
template <int NC, bool L0F>
__global__ void __launch_bounds__(256, 2) k_gemm(const float* __restrict__ bias) {
    extern __shared__ unsigned char sm[];
    const int SA = 1024;
    const int SB = 1024 + 3 * 16384;
    int tid = threadIdx.x;
    int wid = tid >> 5, lane = tid & 31;
    int wm = (wid & 3) * 32, wn = (wid >> 2) * 64;
    uint32_t smb = smem_u32(sm);
    const unsigned short* wimg = L0F ? d_Wimg0 : d_Wimg1;

    // tiles handled by this CTA: bid, bid+GGRID, ...
    int bid = blockIdx.x;
    int nt = 0;
    for (int t = bid; t < NTILES; t += GGRID) nt++;
    const int total = nt * NC;

    auto Abase = [&](int t, int c, int rowl) -> const unsigned short* {
        size_t r = (size_t)(t * 128 + rowl);
        if (L0F) return (c == 0 ? d_h0x : d_h0z) + r * 64;
        else     return (c < 2 ? d_h1 + c * 64 : d_h1z + (c - 2) * 64) + r * 128;
    };

    // A chunk prefetch into ring stage s (XOR swizzled rows of 128B)
    int pi = 0;  // global prefetch chunk counter
    auto issueA = [&]() {
        if (pi < total) {
            int t = bid + (pi / NC) * GGRID;
            int c = pi % NC;
            int s = pi % 3;
#pragma unroll
            for (int i = 0; i < 4; i++) {
                int seg = tid + i * 256;
                int rowl = seg >> 3, q = seg & 7;
                cpa16(smb + SA + s * 16384 + rowl * 128 + ((q ^ (rowl & 7)) << 4),
                      Abase(t, c, rowl) + q * 8);
            }
            pi++;
        }
        CPA_COMMIT();
    };

    // resident B copy (already swizzled in global image) + bias
    {
        const unsigned char* bsrc = (const unsigned char*)wimg;
        for (int seg = tid; seg < NC * 1024; seg += 256)
            cpa16(smb + SB + seg * 16, bsrc + seg * 16);
        CPA_COMMIT();
        if (tid < 128) ((float*)sm)[tid] = bias[tid];
    }
    issueA();
    issueA();

    int a_r = wm + (lane & 15);
    int a_k = (lane >> 4) << 3;
    int b_n = wn + (lane & 7) + ((lane >> 4) << 3);
    int b_k = ((lane >> 3) & 1) << 3;

    float acc[2][8][4];
    int ci = 0;  // global compute chunk counter
    for (int t = bid; t < NTILES; t += GGRID) {
#pragma unroll
        for (int m = 0; m < 2; m++)
#pragma unroll
            for (int nf = 0; nf < 8; nf++)
#pragma unroll
                for (int q = 0; q < 4; q++) acc[m][nf][q] = 0.f;

#pragma unroll
        for (int c = 0; c < NC; c++, ci++) {
            CPA_WAIT1();
            __syncthreads();
            issueA();   // chunk ci+2 -> stage (ci+2)%3, disjoint from (ci)%3 and (ci+1)%3
            uint32_t aB = smb + SA + (ci % 3) * 16384;
            uint32_t bB = smb + SB + c * 16384;
#pragma unroll
            for (int ks = 0; ks < 4; ks++) {
                int k0 = ks * 16;
                uint32_t ah[2][4];
#pragma unroll
                for (int m = 0; m < 2; m++) {
                    int row = a_r + m * 16;
                    int cc = (k0 + a_k) >> 3;
                    ldmat4(ah[m], aB + (uint32_t)(row * 128 + ((cc ^ (row & 7)) << 4)));
                }
                uint32_t bh[8][2];
#pragma unroll
                for (int g = 0; g < 4; g++) {
                    int row = b_n + g * 16;
                    int cc = (k0 + b_k) >> 3;
                    uint32_t tr[4];
                    ldmat4(tr, bB + (uint32_t)(row * 128 + ((cc ^ (row & 7)) << 4)));
                    bh[2 * g][0] = tr[0]; bh[2 * g][1] = tr[1];
                    bh[2 * g + 1][0] = tr[2]; bh[2 * g + 1][1] = tr[3];
                }
#pragma unroll
                for (int m = 0; m < 2; m++)
#pragma unroll
                    for (int nf = 0; nf < 8; nf++) mma_f16(acc[m][nf], ah[m], bh[nf]);
            }
        }

        // epilogue (overlaps with already-issued prefetches of next tile)
        const float* sbias = (const float*)sm;
#pragma unroll
        for (int m = 0; m < 2; m++) {
            int r0 = t * 128 + wm + m * 16 + (lane >> 2);
#pragma unroll
            for (int nf = 0; nf < 8; nf++) {
                int col = wn + nf * 8 + (lane & 3) * 2;
                float bx = sbias[col], by = sbias[col + 1];
                float o0 = acc[m][nf][0] + bx, o1 = acc[m][nf][1] + by;
                float o2 = acc[m][nf][2] + bx, o3 = acc[m][nf][3] + by;
                if (L0F) {
                    o0 = (o0 >= 0.f) ? o0 : 0.2f * o0;
                    o1 = (o1 >= 0.f) ? o1 : 0.2f * o1;
                    o2 = (o2 >= 0.f) ? o2 : 0.2f * o2;
                    o3 = (o3 >= 0.f) ? o3 : 0.2f * o3;
                }
                if (r0 < NROWS)
                    *(uint32_t*)(d_h1 + (size_t)r0 * 128 + col) = pkh(o0, o1);
                if (r0 + 8 < NROWS)
                    *(uint32_t*)(d_h1 + (size_t)(r0 + 8) * 128 + col) = pkh(o2, o3);
            }
        }
    }
}

// ---------------- final: pool(out1 fp16) + (pool(x) @ W_res + sw * b_res) ----------------
__global__ void __launch_bounds__(256) k_final(const float* __restrict__ x,
                                               const int* __restrict__ asgnIdx,
                                               const float* __restrict__ asgnVal,
                                               const float* __restrict__ Wres,
                                               const float* __restrict__ bres,
                                               float* __restrict__ out) {
    __shared__ float xps[4][64];
    if (blockIdx.x == 0 && threadIdx.x == 0) { d_barA = 0; d_barB = 0; }  // reset for next replay
    int sub = threadIdx.x >> 6;
    int p = threadIdx.x & 63;
    int r = blockIdx.x * 4 + sub;
    bool ok = r < 2 * CN;
    int c = r >> 1, b = r & 1;
    const int* fine = asgnIdx + NV;
    float sw = 0.f;
    float2 p1 = make_float2(0.f, 0.f);
    if (ok) {
        int i0 = 4 * c;
        float a = 0.f;
#pragma unroll
        for (int j = 0; j < 4; j++) {
            int f = fine[i0 + j];
            float w = asgnVal[i0 + j];
            a = fmaf(w, x[((size_t)b * NV + f) * 64 + p], a);
            sw += w;
            uint32_t q = *(const uint32_t*)(d_h1 + ((size_t)(2 * f + b)) * 128 + 2 * p);
            float2 o1 = h2f(q);
            p1.x = fmaf(w, o1.x, p1.x);
            p1.y = fmaf(w, o1.y, p1.y);
        }
        xps[sub][p] = a;
    }
    __syncthreads();
    if (ok) {
        float2 br = *(const float2*)(bres + 2 * p);
        float accx = p1.x + sw * br.x;
        float accy = p1.y + sw * br.y;
#pragma unroll 8
        for (int k = 0; k < 64; k++) {
            float xk = xps[sub][k];
            float2 w2 = *(const float2*)(Wres + k * 128 + 2 * p);
            accx = fmaf(xk, w2.x, accx);
            accy = fmaf(xk, w2.y, accy);
        }
        *(float2*)(out + ((size_t)b * CN + c) * 128 + 2 * p) = make_float2(accx, accy);
    }
}

// ---------------- launch ----------------
extern "C" void kernel_launch(void* const* d_in, const int* in_sizes, int n_in,
                              void* d_out, int out_size) {
    const float* x       = (const float*)d_in[0];
    const float* adjVal  = (const float*)d_in[1];
    const float* edgeOne = (const float*)d_in[2];
    const int*   E_start = (const int*)d_in[3];
    const int*   E_end   = (const int*)d_in[4];
    const int*   asgnIdx = (const int*)d_in[5];
    const float* asgnVal = (const float*)d_in[6];
    const float* W_res   = (const float*)d_in[7];
    const float* b_res   = (const float*)d_in[8];
    const float* W0s     = (const float*)d_in[9];
    const float* W0n     = (const float*)d_in[10];
    const float* b0      = (const float*)d_in[11];
    const float* W1s     = (const float*)d_in[12];
    const float* W1n     = (const float*)d_in[13];
    const float* b1      = (const float*)d_in[14];
    float* out = (float*)d_out;

    const int smG0 = 1024 + 3 * 16384 + 2 * 16384;   // 82944
    const int smG1 = 1024 + 3 * 16384 + 4 * 16384;   // 115712 (x2 = 231424, fits 2/SM)
    cudaFuncSetAttribute(k_gemm<2, true>,  cudaFuncAttributeMaxDynamicSharedMemorySize, smG0);
    cudaFuncSetAttribute(k_gemm<4, false>, cudaFuncAttributeMaxDynamicSharedMemorySize, smG1);

    k_prep<<<PPB, 256>>>(W0s, W0n, W1s, W1n, x, E_start, edgeOne); // 0
    k_scanfill<<<SFB, 512>>>(E_start, E_end, adjVal);              // 1
    k_gather64<<<NV / 8, 256>>>();                                 // 2
    k_gemm<2, true><<<GGRID, 256, smG0>>>(b0);                     // 3 <- ncu capture slot
    k_gather128<<<NV / 8, 256>>>();                                // 4
    k_gemm<4, false><<<GGRID, 256, smG1>>>(b1);                    // 5
    k_final<<<(2 * CN + 3) / 4, 256>>>(x, asgnIdx, asgnVal, W_res, b_res, out); // 6
}